// round 13
// baseline (speedup 1.0000x reference)
#include <cuda_runtime.h>
#include <cuda_bf16.h>

// Gumbel-softmax palette quantization, fused single pass.
// probs = softmax((images + gumbel)/T, axis=k);  out = einsum('bhwk,bkc->bhwc', probs, palettes)
// gumbel = -log(-log(u+EPS)+EPS);  single pass (no max-subtract), out_c = (sum p*pal_c)/(sum p)
//
// R3: single-wave persistent grid. R4: f32x2 packed FMAs, lg2-domain gexp (best: 162.6us).
// R5 (reverted): 4px/warp front-batched 16 LDGs -> L1tex queue spread, regression.
// R6/R8: software-pipelined prefetch (MLP 4->8 across iterations, no front-batching),
//     launch_bounds(256,5). redux.sync.add.f32 is NOT available on sm_103a (ptxas
//     rejects) -> 5-value SHFL butterfly as in R4.

#define KDIM 256
#define CDIM 4
#define EPSF 1e-20f
#define LN2F 0.69314718055994530942f
#define LOG2EF 1.44269504088896340736f

typedef unsigned long long u64;

__device__ __forceinline__ float lg2f(float x) {
    float r; asm("lg2.approx.f32 %0, %1;" : "=f"(r) : "f"(x)); return r;
}
__device__ __forceinline__ float ex2f(float x) {
    float r; asm("ex2.approx.f32 %0, %1;" : "=f"(r) : "f"(x)); return r;
}
__device__ __forceinline__ u64 pack2(float lo, float hi) {
    u64 r; asm("mov.b64 %0, {%1, %2};" : "=l"(r) : "f"(lo), "f"(hi)); return r;
}
__device__ __forceinline__ float2 unpack2(u64 v) {
    float2 r; asm("mov.b64 {%0, %1}, %2;" : "=f"(r.x), "=f"(r.y) : "l"(v)); return r;
}
__device__ __forceinline__ u64 fma2(u64 a, u64 b, u64 c) {
    u64 d; asm("fma.rn.f32x2 %0, %1, %2, %3;" : "=l"(d) : "l"(a), "l"(b), "l"(c)); return d;
}
__device__ __forceinline__ u64 add2(u64 a, u64 b) {
    u64 d; asm("add.rn.f32x2 %0, %1, %2;" : "=l"(d) : "l"(a), "l"(b)); return d;
}

// pe = exp((x - log(-log(u+eps)+eps)) * invT) in log2 domain.
__device__ __forceinline__ float gexp(float x, float u, float c1, float c2) {
    float t1 = lg2f(u + EPSF);
    float w  = fmaf(t1, -LN2F, EPSF);
    float t2 = lg2f(w);
    return ex2f(fmaf(x, c1, t2 * c2));
}

__global__ __launch_bounds__(256, 5)
void gsq_kernel(const float* __restrict__ images,
                const float* __restrict__ palettes,
                const float* __restrict__ noise,
                const float* __restrict__ temp,
                float* __restrict__ out,
                int hw)
{
    __shared__ ulonglong2 spal[256];  // 4KB; permuted: (elem j, lane) at [j*32+lane]

    const int lane = threadIdx.x & 31;
    const int wid  = threadIdx.x >> 5;
    const int batch = blockIdx.y;
    const int warps_per_block = blockDim.x >> 5;
    const int warp_global = blockIdx.x * warps_per_block + wid;
    const int warp_stride = gridDim.x * warps_per_block;   // warps per batch

    const float invT = __fdividef(1.0f, temp[0]);
    const float c1 = invT * LOG2EF;
    const float c2 = -invT;

    // Conflict-free permuted palette: spal[(j<<5)+lane] = pal[4*lane+j] (+128 hi half)
    {
        const float4* __restrict__ pal =
            (const float4*)(palettes + (size_t)batch * KDIM * CDIM);
        int e = threadIdx.x;
        int el = e & 127;
        int dst = (e & 128) + ((el & 3) << 5) + (el >> 2);
        ((float4*)spal)[dst] = pal[e];
    }
    __syncthreads();

    const size_t base_b = (size_t)batch * hw * KDIM;
    const float4* ip = (const float4*)(images + base_b) + (size_t)warp_global * 64 + lane;
    const float4* np = (const float4*)(noise  + base_b) + (size_t)warp_global * 64 + lane;
    float4*      outp = (float4*)out + (size_t)batch * hw + warp_global;
    const size_t step = (size_t)warp_stride * 64;

    const int iters = (hw - 1 - warp_global) / warp_stride + 1;

    // Per-pixel compute + reduce + store (R4 body).
    auto compute = [&](float4 a0, float4 a1, float4 n0, float4 n1) {
        u64 accA = 0, accB = 0, s2 = 0;
        float pe0, pe1; u64 d; ulonglong2 P;

        pe0 = gexp(a0.x, n0.x, c1, c2);
        pe1 = gexp(a0.y, n0.y, c1, c2);
        s2 = add2(s2, pack2(pe0, pe1));
        P = spal[lane];       d = pack2(pe0, pe0);
        accA = fma2(d, P.x, accA); accB = fma2(d, P.y, accB);
        P = spal[32 + lane];  d = pack2(pe1, pe1);
        accA = fma2(d, P.x, accA); accB = fma2(d, P.y, accB);

        pe0 = gexp(a0.z, n0.z, c1, c2);
        pe1 = gexp(a0.w, n0.w, c1, c2);
        s2 = add2(s2, pack2(pe0, pe1));
        P = spal[64 + lane];  d = pack2(pe0, pe0);
        accA = fma2(d, P.x, accA); accB = fma2(d, P.y, accB);
        P = spal[96 + lane];  d = pack2(pe1, pe1);
        accA = fma2(d, P.x, accA); accB = fma2(d, P.y, accB);

        pe0 = gexp(a1.x, n1.x, c1, c2);
        pe1 = gexp(a1.y, n1.y, c1, c2);
        s2 = add2(s2, pack2(pe0, pe1));
        P = spal[128 + lane]; d = pack2(pe0, pe0);
        accA = fma2(d, P.x, accA); accB = fma2(d, P.y, accB);
        P = spal[160 + lane]; d = pack2(pe1, pe1);
        accA = fma2(d, P.x, accA); accB = fma2(d, P.y, accB);

        pe0 = gexp(a1.z, n1.z, c1, c2);
        pe1 = gexp(a1.w, n1.w, c1, c2);
        s2 = add2(s2, pack2(pe0, pe1));
        P = spal[192 + lane]; d = pack2(pe0, pe0);
        accA = fma2(d, P.x, accA); accB = fma2(d, P.y, accB);
        P = spal[224 + lane]; d = pack2(pe1, pe1);
        accA = fma2(d, P.x, accA); accB = fma2(d, P.y, accB);

        // 5-value butterfly reduction across the warp (SHFL; redux.f32 absent on sm_103a)
        float2 sp = unpack2(s2);
        float s = sp.x + sp.y;
#pragma unroll
        for (int off = 16; off > 0; off >>= 1) {
            s += __shfl_xor_sync(0xffffffffu, s, off);
            float2 ua = unpack2(accA);
            float2 ub = unpack2(accB);
            accA = add2(accA, pack2(__shfl_xor_sync(0xffffffffu, ua.x, off),
                                    __shfl_xor_sync(0xffffffffu, ua.y, off)));
            accB = add2(accB, pack2(__shfl_xor_sync(0xffffffffu, ub.x, off),
                                    __shfl_xor_sync(0xffffffffu, ub.y, off)));
        }

        if (lane == 0) {
            float inv = __fdividef(1.0f, s);
            float2 oa = unpack2(accA);
            float2 ob = unpack2(accB);
            float4 o;
            o.x = oa.x * inv; o.y = oa.y * inv;
            o.z = ob.x * inv; o.w = ob.y * inv;
            *outp = o;
        }
        outp += warp_stride;
    };

    // Software pipeline: prefetch iteration i+1's 4 loads before computing i.
    float4 a0 = __ldcs(ip);
    float4 a1 = __ldcs(ip + 32);
    float4 n0 = __ldcs(np);
    float4 n1 = __ldcs(np + 32);

    for (int i = 0; i < iters - 1; ++i) {
        ip += step; np += step;
        float4 b0 = __ldcs(ip);
        float4 b1 = __ldcs(ip + 32);
        float4 m0 = __ldcs(np);
        float4 m1 = __ldcs(np + 32);

        compute(a0, a1, n0, n1);

        a0 = b0; a1 = b1; n0 = m0; n1 = m1;
    }
    compute(a0, a1, n0, n1);
}

extern "C" void kernel_launch(void* const* d_in, const int* in_sizes, int n_in,
                              void* d_out, int out_size) {
    const float* images   = (const float*)d_in[0];
    const float* palettes = (const float*)d_in[1];
    const float* noise    = (const float*)d_in[2];
    const float* temp     = (const float*)d_in[3];
    float* out = (float*)d_out;

    int batches = in_sizes[1] / (KDIM * CDIM);               // 8
    int hw = (int)(in_sizes[0] / ((size_t)batches * KDIM));  // 65536

    dim3 block(256, 1, 1);
    // Single full wave at 5 blocks/SM: 148x5=740 -> use 92x8=736 blocks (<=740).
    dim3 grid(92, batches, 1);
    gsq_kernel<<<grid, block>>>(images, palettes, noise, temp, out, hw);
}

// round 14
// speedup vs baseline: 2.6044x; 2.6044x over previous
#include <cuda_runtime.h>
#include <cuda_bf16.h>

// Gumbel-softmax palette quantization, fused single pass.
// probs = softmax((images + gumbel)/T, axis=k);  out = einsum('bhwk,bkc->bhwc', probs, palettes)
// gumbel = -log(-log(u+EPS)+EPS);  single pass (no max-subtract), out_c = (sum p*pal_c)/(sum p)
//
// R3: single-wave persistent grid. R4: f32x2 packed FMAs, lg2-domain gexp -> BEST (162.6us),
//     runs at exactly traffic/achieved-BW (1.08GB @ 6.5TB/s) => at the HBM streaming floor.
// R5 (front-batched 16 LDG) and R13 (sw-pipeline w/ lambda) both regressed -> R4 loop
//     schedule is the local optimum; do not restructure.
// R14: exact R4 restore + __stcs streaming store (output never re-read).

#define KDIM 256
#define CDIM 4
#define EPSF 1e-20f
#define LN2F 0.69314718055994530942f
#define LOG2EF 1.44269504088896340736f

typedef unsigned long long u64;

__device__ __forceinline__ float lg2f(float x) {
    float r; asm("lg2.approx.f32 %0, %1;" : "=f"(r) : "f"(x)); return r;
}
__device__ __forceinline__ float ex2f(float x) {
    float r; asm("ex2.approx.f32 %0, %1;" : "=f"(r) : "f"(x)); return r;
}
__device__ __forceinline__ u64 pack2(float lo, float hi) {
    u64 r; asm("mov.b64 %0, {%1, %2};" : "=l"(r) : "f"(lo), "f"(hi)); return r;
}
__device__ __forceinline__ float2 unpack2(u64 v) {
    float2 r; asm("mov.b64 {%0, %1}, %2;" : "=f"(r.x), "=f"(r.y) : "l"(v)); return r;
}
__device__ __forceinline__ u64 fma2(u64 a, u64 b, u64 c) {
    u64 d; asm("fma.rn.f32x2 %0, %1, %2, %3;" : "=l"(d) : "l"(a), "l"(b), "l"(c)); return d;
}
__device__ __forceinline__ u64 add2(u64 a, u64 b) {
    u64 d; asm("add.rn.f32x2 %0, %1, %2;" : "=l"(d) : "l"(a), "l"(b)); return d;
}

// pe = exp((x - log(-log(u+eps)+eps)) * invT), computed in log2 domain:
// t1 = lg2(u+eps); w = eps - t1*ln2; t2 = lg2(w); pe = ex2(x*c1 + t2*c2)
// with c1 = invT*log2e, c2 = -invT.
__device__ __forceinline__ float gexp(float x, float u, float c1, float c2) {
    float t1 = lg2f(u + EPSF);
    float w  = fmaf(t1, -LN2F, EPSF);
    float t2 = lg2f(w);
    return ex2f(fmaf(x, c1, t2 * c2));
}

__global__ __launch_bounds__(256, 6)
void gsq_kernel(const float* __restrict__ images,
                const float* __restrict__ palettes,
                const float* __restrict__ noise,
                const float* __restrict__ temp,
                float* __restrict__ out,
                int hw)
{
    __shared__ ulonglong2 spal[256];  // 4KB; permuted: entry for (elem j, lane) at [j*32+lane]

    const int lane = threadIdx.x & 31;
    const int wid  = threadIdx.x >> 5;
    const int batch = blockIdx.y;
    const int warps_per_block = blockDim.x >> 5;
    const int warp_global = blockIdx.x * warps_per_block + wid;
    const int warp_stride = gridDim.x * warps_per_block;   // 888 warps per batch

    const float invT = __fdividef(1.0f, temp[0]);
    const float c1 = invT * LOG2EF;
    const float c2 = -invT;

    // Fill smem palette, permuted so consecutive lanes hit consecutive 16B
    // (conflict-free LDS.128). spal[(j<<5)+lane] = pal[4*lane+j] (+128 for hi half).
    {
        const float4* __restrict__ pal =
            (const float4*)(palettes + (size_t)batch * KDIM * CDIM);
        int e = threadIdx.x;
        int el = e & 127;
        int dst = (e & 128) + ((el & 3) << 5) + (el >> 2);
        ((float4*)spal)[dst] = pal[e];
    }
    __syncthreads();

    const size_t base_b = (size_t)batch * hw * KDIM;
    const float4* img = (const float4*)(images + base_b) + (size_t)warp_global * 64 + lane;
    const float4* nse = (const float4*)(noise  + base_b) + (size_t)warp_global * 64 + lane;
    float4*       outp = (float4*)out + (size_t)batch * hw + warp_global;
    const size_t  step = (size_t)warp_stride * 64;

    for (int p = warp_global; p < hw; p += warp_stride,
                                       img += step, nse += step, outp += warp_stride) {
        // 4 independent 512B-coalesced streaming loads (MLP=4), no cache pollution
        float4 a0 = __ldcs(img);
        float4 a1 = __ldcs(img + 32);
        float4 n0 = __ldcs(nse);
        float4 n1 = __ldcs(nse + 32);

        u64 accA = 0, accB = 0, s2 = 0;   // packed (x,y), (z,w), (s_even,s_odd)
        float pe0, pe1; u64 d; ulonglong2 P;

        pe0 = gexp(a0.x, n0.x, c1, c2);
        pe1 = gexp(a0.y, n0.y, c1, c2);
        s2 = add2(s2, pack2(pe0, pe1));
        P = spal[lane];       d = pack2(pe0, pe0);
        accA = fma2(d, P.x, accA); accB = fma2(d, P.y, accB);
        P = spal[32 + lane];  d = pack2(pe1, pe1);
        accA = fma2(d, P.x, accA); accB = fma2(d, P.y, accB);

        pe0 = gexp(a0.z, n0.z, c1, c2);
        pe1 = gexp(a0.w, n0.w, c1, c2);
        s2 = add2(s2, pack2(pe0, pe1));
        P = spal[64 + lane];  d = pack2(pe0, pe0);
        accA = fma2(d, P.x, accA); accB = fma2(d, P.y, accB);
        P = spal[96 + lane];  d = pack2(pe1, pe1);
        accA = fma2(d, P.x, accA); accB = fma2(d, P.y, accB);

        pe0 = gexp(a1.x, n1.x, c1, c2);
        pe1 = gexp(a1.y, n1.y, c1, c2);
        s2 = add2(s2, pack2(pe0, pe1));
        P = spal[128 + lane]; d = pack2(pe0, pe0);
        accA = fma2(d, P.x, accA); accB = fma2(d, P.y, accB);
        P = spal[160 + lane]; d = pack2(pe1, pe1);
        accA = fma2(d, P.x, accA); accB = fma2(d, P.y, accB);

        pe0 = gexp(a1.z, n1.z, c1, c2);
        pe1 = gexp(a1.w, n1.w, c1, c2);
        s2 = add2(s2, pack2(pe0, pe1));
        P = spal[192 + lane]; d = pack2(pe0, pe0);
        accA = fma2(d, P.x, accA); accB = fma2(d, P.y, accB);
        P = spal[224 + lane]; d = pack2(pe1, pe1);
        accA = fma2(d, P.x, accA); accB = fma2(d, P.y, accB);

        // Butterfly reduction: s scalar + two packed pairs (5 SHFL + 2 ADD2 + 1 FADD per stage)
        float2 sp = unpack2(s2);
        float s = sp.x + sp.y;
#pragma unroll
        for (int off = 16; off > 0; off >>= 1) {
            s += __shfl_xor_sync(0xffffffffu, s, off);
            float2 ua = unpack2(accA);
            float2 ub = unpack2(accB);
            accA = add2(accA, pack2(__shfl_xor_sync(0xffffffffu, ua.x, off),
                                    __shfl_xor_sync(0xffffffffu, ua.y, off)));
            accB = add2(accB, pack2(__shfl_xor_sync(0xffffffffu, ub.x, off),
                                    __shfl_xor_sync(0xffffffffu, ub.y, off)));
        }

        if (lane == 0) {
            float inv = __fdividef(1.0f, s);
            float2 oa = unpack2(accA);
            float2 ob = unpack2(accB);
            float4 o;
            o.x = oa.x * inv; o.y = oa.y * inv;
            o.z = ob.x * inv; o.w = ob.y * inv;
            __stcs(outp, o);   // streaming store: output is never re-read
        }
    }
}

extern "C" void kernel_launch(void* const* d_in, const int* in_sizes, int n_in,
                              void* d_out, int out_size) {
    const float* images   = (const float*)d_in[0];
    const float* palettes = (const float*)d_in[1];
    const float* noise    = (const float*)d_in[2];
    const float* temp     = (const float*)d_in[3];
    float* out = (float*)d_out;

    int batches = in_sizes[1] / (KDIM * CDIM);               // 8
    int hw = (int)(in_sizes[0] / ((size_t)batches * KDIM));  // 65536

    dim3 block(256, 1, 1);
    // Single full wave: 148 SMs x 6 resident blocks = 888 blocks = 111 x 8 batches.
    dim3 grid(111, batches, 1);
    gsq_kernel<<<grid, block>>>(images, palettes, noise, temp, out, hw);
}